// round 3
// baseline (speedup 1.0000x reference)
#include <cuda_runtime.h>
#include <cstdint>

#define NROWS 8192
#define DDIM  256
#define KN    10

// ---------------- scratch (static device globals; no allocation) ----------------
__device__ float g_Fn[(size_t)NROWS * DDIM];      // feats[j] / ||feats[j]||
__device__ float g_sim[(size_t)NROWS * NROWS];    // ordering scores (256 MB)
__device__ int   g_topk[NROWS * KN];
__device__ int   g_dv[NROWS];
__device__ float g_invdv[NROWS];

// ---------------- kernel 1: row norms -> normalized matrix; zero dv ----------------
__global__ __launch_bounds__(256) void k_normalize(const float* __restrict__ feats) {
    int warp = (blockIdx.x * blockDim.x + threadIdx.x) >> 5;
    int lane = threadIdx.x & 31;
    if (warp < NROWS) {
        const float* x = feats + (size_t)warp * DDIM;
        float s = 0.f;
        #pragma unroll
        for (int k = lane; k < DDIM; k += 32) { float v = x[k]; s += v * v; }
        #pragma unroll
        for (int off = 16; off; off >>= 1) s += __shfl_xor_sync(0xffffffffu, s, off);
        float inv = 1.0f / sqrtf(s);
        #pragma unroll
        for (int k = lane; k < DDIM; k += 32)
            g_Fn[(size_t)warp * DDIM + k] = x[k] * inv;
    }
    int gt = blockIdx.x * blockDim.x + threadIdx.x;
    if (gt < NROWS) g_dv[gt] = 0;
}

// ---------------- kernel 2: g_sim[i,j] = sum_k feats[i,k]*g_Fn[j,k] (SGEMM-NT 128x128x8)
// NOTE: device globals are referenced INSIDE the kernel (never passed from host —
// host-side symbol address is the shadow, not the device address).
#define BM 128
#define BN 128
#define BK 8
#define TM 8
#define TN 8

__global__ __launch_bounds__(256) void k_gemm_nt(const float* __restrict__ A) {
    __shared__ float As[BK][BM + 4];
    __shared__ float Bs[BK][BN + 4];
    const float* B = g_Fn;
    float* C = g_sim;

    int bm = blockIdx.y * BM;
    int bn = blockIdx.x * BN;
    int tid = threadIdx.x;
    int lr = tid >> 1;            // 0..127
    int lk = (tid & 1) << 2;      // 0 or 4
    int tx = tid & 15;
    int ty = tid >> 4;

    float acc[TM][TN];
    #pragma unroll
    for (int m = 0; m < TM; m++)
        #pragma unroll
        for (int n = 0; n < TN; n++) acc[m][n] = 0.f;

    const float* Ap = A + (size_t)(bm + lr) * DDIM + lk;
    const float* Bp = B + (size_t)(bn + lr) * DDIM + lk;

    for (int k0 = 0; k0 < DDIM; k0 += BK) {
        float4 a4 = *(const float4*)(Ap + k0);
        float4 b4 = *(const float4*)(Bp + k0);
        As[lk + 0][lr] = a4.x; As[lk + 1][lr] = a4.y;
        As[lk + 2][lr] = a4.z; As[lk + 3][lr] = a4.w;
        Bs[lk + 0][lr] = b4.x; Bs[lk + 1][lr] = b4.y;
        Bs[lk + 2][lr] = b4.z; Bs[lk + 3][lr] = b4.w;
        __syncthreads();
        #pragma unroll
        for (int k = 0; k < BK; k++) {
            float ra[TM], rb[TN];
            *(float4*)(ra)     = *(const float4*)&As[k][ty * TM];
            *(float4*)(ra + 4) = *(const float4*)&As[k][ty * TM + 4];
            *(float4*)(rb)     = *(const float4*)&Bs[k][tx * TN];
            *(float4*)(rb + 4) = *(const float4*)&Bs[k][tx * TN + 4];
            #pragma unroll
            for (int m = 0; m < TM; m++)
                #pragma unroll
                for (int n = 0; n < TN; n++)
                    acc[m][n] += ra[m] * rb[n];
        }
        __syncthreads();
    }

    #pragma unroll
    for (int m = 0; m < TM; m++) {
        size_t roff = (size_t)(bm + ty * TM + m) * NROWS + bn + tx * TN;
        float4 v0 = make_float4(acc[m][0], acc[m][1], acc[m][2], acc[m][3]);
        float4 v1 = make_float4(acc[m][4], acc[m][5], acc[m][6], acc[m][7]);
        *(float4*)&C[roff]     = v0;
        *(float4*)&C[roff + 4] = v1;
    }
}

// ---------------- kernel 3: per-row top-10 (one warp per row), accumulate dv ----------------
__global__ __launch_bounds__(128) void k_topk() {
    int row  = blockIdx.x * 4 + (threadIdx.x >> 5);
    int lane = threadIdx.x & 31;
    const float* s = g_sim + (size_t)row * NROWS;

    const float NEG_INF = __int_as_float(0xff800000);
    float bv[KN]; int bi[KN];
    #pragma unroll
    for (int t = 0; t < KN; t++) { bv[t] = NEG_INF; bi[t] = 0x7fffffff; }

    // local top-10 per lane; j ascends within a lane so ties keep lower index
    for (int j = lane; j < NROWS; j += 32) {
        float v = s[j];
        if (v > bv[KN - 1]) {
            float cv = v; int ci = j;
            #pragma unroll
            for (int t = 0; t < KN; t++) {
                bool better = (cv > bv[t]) || (cv == bv[t] && ci < bi[t]);
                if (better) {
                    float tv = bv[t]; int ti = bi[t];
                    bv[t] = cv; bi[t] = ci;
                    cv = tv; ci = ti;
                }
            }
        }
    }

    // 10 rounds of warp argmax ((v desc, idx asc) comparator) with pop
    #pragma unroll 1
    for (int r = 0; r < KN; r++) {
        float mv = bv[0]; int mi = bi[0];
        #pragma unroll
        for (int off = 16; off; off >>= 1) {
            float ov = __shfl_xor_sync(0xffffffffu, mv, off);
            int   oi = __shfl_xor_sync(0xffffffffu, mi, off);
            if (ov > mv || (ov == mv && oi < mi)) { mv = ov; mi = oi; }
        }
        if (mi == bi[0]) {  // indices unique across lanes -> winner pops its head
            #pragma unroll
            for (int t = 0; t < KN - 1; t++) { bv[t] = bv[t + 1]; bi[t] = bi[t + 1]; }
            bv[KN - 1] = NEG_INF; bi[KN - 1] = 0x7fffffff;
        }
        if (lane == 0) {
            g_topk[row * KN + r] = mi;
            atomicAdd(&g_dv[mi], 1);
        }
    }
}

// ---------------- kernel 4: inv_dv ----------------
__global__ void k_invdv() {
    int i = blockIdx.x * blockDim.x + threadIdx.x;
    if (i < NROWS) {
        int d = g_dv[i];
        g_invdv[i] = d > 0 ? 1.0f / sqrtf((float)d) : 0.0f;
    }
}

// ---------------- kernel 5: zero the output ----------------
__global__ void k_zero(float4* __restrict__ out) {
    size_t i = (size_t)blockIdx.x * blockDim.x + threadIdx.x;
    size_t stride = (size_t)gridDim.x * blockDim.x;
    size_t n4 = (size_t)NROWS * NROWS / 4;
    for (; i < n4; i += stride) out[i] = make_float4(0.f, 0.f, 0.f, 0.f);
}

// ---------------- kernel 6: scatter 10x10 outer products per hyperedge ----------------
__global__ __launch_bounds__(128) void k_scatter(float* __restrict__ out) {
    __shared__ int   sidx[KN];
    __shared__ float sw[KN];
    int e = blockIdx.x;
    int t = threadIdx.x;
    if (t < KN) {
        int a = g_topk[e * KN + t];
        sidx[t] = a;
        sw[t] = g_invdv[a];
    }
    __syncthreads();
    if (t < KN * KN) {
        int a = sidx[t / KN];
        int b = sidx[t % KN];
        // same association as reference: (inv_dv[a]*inv_de) * inv_dv[b]
        float val = (0.1f * sw[t / KN]) * sw[t % KN];
        atomicAdd(&out[(size_t)a * NROWS + b], val);
    }
}

// ---------------- launch ----------------
extern "C" void kernel_launch(void* const* d_in, const int* in_sizes, int n_in,
                              void* d_out, int out_size) {
    const float* feats = (const float*)d_in[0];
    float* out = (float*)d_out;

    k_normalize<<<(NROWS * 32) / 256, 256>>>(feats);

    dim3 grid(NROWS / BN, NROWS / BM);
    k_gemm_nt<<<grid, 256>>>(feats);

    k_zero<<<2048, 256>>>((float4*)out);

    k_topk<<<NROWS / 4, 128>>>();
    k_invdv<<<NROWS / 256, 256>>>();
    k_scatter<<<NROWS, 128>>>(out);
}

// round 4
// speedup vs baseline: 1.0754x; 1.0754x over previous
#include <cuda_runtime.h>
#include <cstdint>

#define NROWS 8192
#define DDIM  256
#define KN    10

// ---------------- scratch (static device globals; no allocation) ----------------
__device__ float g_Fn[(size_t)NROWS * DDIM];      // feats[j] / ||feats[j]||
__device__ float g_sim[(size_t)NROWS * NROWS];    // ordering scores (256 MB)
__device__ int   g_topk[NROWS * KN];
__device__ int   g_dv[NROWS];
__device__ float g_invdv[NROWS];

// ---------------- kernel 1: row norms -> normalized matrix; zero dv ----------------
__global__ __launch_bounds__(256) void k_normalize(const float* __restrict__ feats) {
    int warp = (blockIdx.x * blockDim.x + threadIdx.x) >> 5;
    int lane = threadIdx.x & 31;
    if (warp < NROWS) {
        const float* x = feats + (size_t)warp * DDIM;
        float s = 0.f;
        #pragma unroll
        for (int k = lane; k < DDIM; k += 32) { float v = x[k]; s += v * v; }
        #pragma unroll
        for (int off = 16; off; off >>= 1) s += __shfl_xor_sync(0xffffffffu, s, off);
        float inv = 1.0f / sqrtf(s);
        #pragma unroll
        for (int k = lane; k < DDIM; k += 32)
            g_Fn[(size_t)warp * DDIM + k] = x[k] * inv;
    }
    int gt = blockIdx.x * blockDim.x + threadIdx.x;
    if (gt < NROWS) g_dv[gt] = 0;
}

// ---------------- kernel 2: g_sim[i,j] = sum_k feats[i,k]*g_Fn[j,k]
// SGEMM-NT 128x128x8, double-buffered smem, packed fma.rn.f32x2 math.
#define BM 128
#define BN 128
#define BK 8
#define TM 8
#define TN 8

__global__ __launch_bounds__(256) void k_gemm_nt(const float* __restrict__ A) {
    __shared__ __align__(16) float As[2][BK][BM + 4];
    __shared__ __align__(16) float Bs[2][BK][BN + 4];
    const float* B = g_Fn;
    float* C = g_sim;

    int bm = blockIdx.y * BM;
    int bn = blockIdx.x * BN;
    int tid = threadIdx.x;
    int lr = tid >> 1;            // 0..127
    int lk = (tid & 1) << 2;      // 0 or 4
    int tx = tid & 15;
    int ty = tid >> 4;

    // packed accumulators: accp[m][p] holds cols {2p, 2p+1} as f32x2 (lo = even col)
    unsigned long long accp[TM][TN / 2];
    #pragma unroll
    for (int m = 0; m < TM; m++)
        #pragma unroll
        for (int p = 0; p < TN / 2; p++) accp[m][p] = 0ull;

    const float* Ap = A + (size_t)(bm + lr) * DDIM + lk;
    const float* Bp = B + (size_t)(bn + lr) * DDIM + lk;

    // preload tile 0
    float4 a4 = *(const float4*)(Ap);
    float4 b4 = *(const float4*)(Bp);
    As[0][lk + 0][lr] = a4.x; As[0][lk + 1][lr] = a4.y;
    As[0][lk + 2][lr] = a4.z; As[0][lk + 3][lr] = a4.w;
    Bs[0][lk + 0][lr] = b4.x; Bs[0][lk + 1][lr] = b4.y;
    Bs[0][lk + 2][lr] = b4.z; Bs[0][lk + 3][lr] = b4.w;
    __syncthreads();

    int cur = 0;
    for (int k0 = BK; k0 <= DDIM; k0 += BK) {
        float4 a4n, b4n;
        bool more = (k0 < DDIM);
        if (more) {
            a4n = *(const float4*)(Ap + k0);
            b4n = *(const float4*)(Bp + k0);
        }
        #pragma unroll
        for (int k = 0; k < BK; k++) {
            float4 ra0 = *(const float4*)&As[cur][k][ty * TM];
            float4 ra1 = *(const float4*)&As[cur][k][ty * TM + 4];
            const ulonglong2* brow = (const ulonglong2*)&Bs[cur][k][tx * TN];
            ulonglong2 bl = brow[0];
            ulonglong2 bh = brow[1];
            unsigned long long rb0 = bl.x, rb1 = bl.y, rb2 = bh.x, rb3 = bh.y;
            float ra[TM] = {ra0.x, ra0.y, ra0.z, ra0.w, ra1.x, ra1.y, ra1.z, ra1.w};
            #pragma unroll
            for (int m = 0; m < TM; m++) {
                unsigned long long ad;
                unsigned int au = __float_as_uint(ra[m]);
                asm("mov.b64 %0, {%1, %1};" : "=l"(ad) : "r"(au));
                asm("fma.rn.f32x2 %0, %1, %2, %0;" : "+l"(accp[m][0]) : "l"(ad), "l"(rb0));
                asm("fma.rn.f32x2 %0, %1, %2, %0;" : "+l"(accp[m][1]) : "l"(ad), "l"(rb1));
                asm("fma.rn.f32x2 %0, %1, %2, %0;" : "+l"(accp[m][2]) : "l"(ad), "l"(rb2));
                asm("fma.rn.f32x2 %0, %1, %2, %0;" : "+l"(accp[m][3]) : "l"(ad), "l"(rb3));
            }
        }
        if (more) {
            int nxt = cur ^ 1;
            As[nxt][lk + 0][lr] = a4n.x; As[nxt][lk + 1][lr] = a4n.y;
            As[nxt][lk + 2][lr] = a4n.z; As[nxt][lk + 3][lr] = a4n.w;
            Bs[nxt][lk + 0][lr] = b4n.x; Bs[nxt][lk + 1][lr] = b4n.y;
            Bs[nxt][lk + 2][lr] = b4n.z; Bs[nxt][lk + 3][lr] = b4n.w;
            __syncthreads();
            cur = nxt;
        }
    }

    #pragma unroll
    for (int m = 0; m < TM; m++) {
        size_t roff = (size_t)(bm + ty * TM + m) * NROWS + bn + tx * TN;
        float c[TN];
        #pragma unroll
        for (int p = 0; p < TN / 2; p++) {
            unsigned int lo, hi;
            asm("mov.b64 {%0, %1}, %2;" : "=r"(lo), "=r"(hi) : "l"(accp[m][p]));
            c[2 * p]     = __uint_as_float(lo);
            c[2 * p + 1] = __uint_as_float(hi);
        }
        *(float4*)&C[roff]     = make_float4(c[0], c[1], c[2], c[3]);
        *(float4*)&C[roff + 4] = make_float4(c[4], c[5], c[6], c[7]);
    }
}

// ---------------- kernel 3: per-row top-10 (one warp per row), accumulate dv ----------------
__device__ __forceinline__ void topk_insert(float v, int j, float bv[KN], int bi[KN]) {
    if (v > bv[KN - 1]) {
        float cv = v; int ci = j;
        #pragma unroll
        for (int t = 0; t < KN; t++) {
            bool better = (cv > bv[t]) || (cv == bv[t] && ci < bi[t]);
            if (better) {
                float tv = bv[t]; int ti = bi[t];
                bv[t] = cv; bi[t] = ci;
                cv = tv; ci = ti;
            }
        }
    }
}

__global__ __launch_bounds__(128) void k_topk() {
    int row  = blockIdx.x * 4 + (threadIdx.x >> 5);
    int lane = threadIdx.x & 31;
    const float4* s4 = (const float4*)(g_sim + (size_t)row * NROWS);

    const float NEG_INF = __int_as_float(0xff800000);
    float bv[KN]; int bi[KN];
    #pragma unroll
    for (int t = 0; t < KN; t++) { bv[t] = NEG_INF; bi[t] = 0x7fffffff; }

    // vectorized scan: 16B per lane per iter; rare insert path guarded by max4.
    // within a lane j ascends, so ties keep the lower index (matches jax top_k).
    #pragma unroll 4
    for (int it = 0; it < NROWS / 128; it++) {
        int j4 = it * 32 + lane;
        float4 v = s4[j4];
        float m = fmaxf(fmaxf(v.x, v.y), fmaxf(v.z, v.w));
        if (m > bv[KN - 1]) {
            int jb = j4 * 4;
            topk_insert(v.x, jb + 0, bv, bi);
            topk_insert(v.y, jb + 1, bv, bi);
            topk_insert(v.z, jb + 2, bv, bi);
            topk_insert(v.w, jb + 3, bv, bi);
        }
    }

    // 10 rounds of warp argmax ((v desc, idx asc) comparator) with pop
    #pragma unroll 1
    for (int r = 0; r < KN; r++) {
        float mv = bv[0]; int mi = bi[0];
        #pragma unroll
        for (int off = 16; off; off >>= 1) {
            float ov = __shfl_xor_sync(0xffffffffu, mv, off);
            int   oi = __shfl_xor_sync(0xffffffffu, mi, off);
            if (ov > mv || (ov == mv && oi < mi)) { mv = ov; mi = oi; }
        }
        if (mi == bi[0]) {  // indices unique across lanes -> winner pops its head
            #pragma unroll
            for (int t = 0; t < KN - 1; t++) { bv[t] = bv[t + 1]; bi[t] = bi[t + 1]; }
            bv[KN - 1] = NEG_INF; bi[KN - 1] = 0x7fffffff;
        }
        if (lane == 0) {
            g_topk[row * KN + r] = mi;
            atomicAdd(&g_dv[mi], 1);
        }
    }
}

// ---------------- kernel 4: inv_dv ----------------
__global__ void k_invdv() {
    int i = blockIdx.x * blockDim.x + threadIdx.x;
    if (i < NROWS) {
        int d = g_dv[i];
        g_invdv[i] = d > 0 ? 1.0f / sqrtf((float)d) : 0.0f;
    }
}

// ---------------- kernel 5: zero the output ----------------
__global__ void k_zero(float4* __restrict__ out) {
    size_t i = (size_t)blockIdx.x * blockDim.x + threadIdx.x;
    size_t stride = (size_t)gridDim.x * blockDim.x;
    size_t n4 = (size_t)NROWS * NROWS / 4;
    for (; i < n4; i += stride) out[i] = make_float4(0.f, 0.f, 0.f, 0.f);
}

// ---------------- kernel 6: scatter 10x10 outer products per hyperedge ----------------
__global__ __launch_bounds__(128) void k_scatter(float* __restrict__ out) {
    __shared__ int   sidx[KN];
    __shared__ float sw[KN];
    int e = blockIdx.x;
    int t = threadIdx.x;
    if (t < KN) {
        int a = g_topk[e * KN + t];
        sidx[t] = a;
        sw[t] = g_invdv[a];
    }
    __syncthreads();
    if (t < KN * KN) {
        int a = sidx[t / KN];
        int b = sidx[t % KN];
        // same association as reference: (inv_dv[a]*inv_de) * inv_dv[b]
        float val = (0.1f * sw[t / KN]) * sw[t % KN];
        atomicAdd(&out[(size_t)a * NROWS + b], val);
    }
}

// ---------------- launch ----------------
extern "C" void kernel_launch(void* const* d_in, const int* in_sizes, int n_in,
                              void* d_out, int out_size) {
    const float* feats = (const float*)d_in[0];
    float* out = (float*)d_out;

    k_normalize<<<(NROWS * 32) / 256, 256>>>(feats);

    dim3 grid(NROWS / BN, NROWS / BM);
    k_gemm_nt<<<grid, 256>>>(feats);

    k_zero<<<2048, 256>>>((float4*)out);

    k_topk<<<NROWS / 4, 128>>>();
    k_invdv<<<NROWS / 256, 256>>>();
    k_scatter<<<NROWS, 128>>>(out);
}

// round 6
// speedup vs baseline: 2.5182x; 2.3416x over previous
#include <cuda_runtime.h>
#include <cuda_fp16.h>
#include <cstdint>

#define NROWS 8192
#define DDIM  256
#define KN    10
#define KTOT  768                 // [Ah | Ah | Al] x [Bh | Bl | Bh]

// ---------------- scratch (static device globals; no allocation) ----------------
__device__ __half g_A3[(size_t)NROWS * KTOT];
__device__ __half g_B3[(size_t)NROWS * KTOT];
__device__ float g_sim[(size_t)NROWS * NROWS];
__device__ int   g_topk[NROWS * KN];
__device__ int   g_dv[NROWS];
__device__ float g_invdv[NROWS];

__device__ __forceinline__ uint32_t smem_u32(const void* p) {
    uint32_t a;
    asm("{ .reg .u64 t; cvta.to.shared.u64 t, %1; cvt.u32.u64 %0, t; }" : "=r"(a) : "l"(p));
    return a;
}

// ---------------- kernel 1: prep — build split-fp16 A3/B3; zero dv ----------------
// a = ah + al (fp16 split), b = a/||a|| = bh + bl
// A3 row = [ah | ah | al], B3 row = [bh | bl | bh]
// => A3·B3^T = ah·bh + ah·bl + al·bh = a·b - al·bl  (al·bl ~ 2^-22 rel: negligible)
__global__ __launch_bounds__(256) void k_prep(const float* __restrict__ feats) {
    int warp = (blockIdx.x * blockDim.x + threadIdx.x) >> 5;
    int lane = threadIdx.x & 31;
    if (warp < NROWS) {
        const float* x = feats + (size_t)warp * DDIM;
        float s = 0.f;
        #pragma unroll
        for (int k = lane; k < DDIM; k += 32) { float v = x[k]; s += v * v; }
        #pragma unroll
        for (int off = 16; off; off >>= 1) s += __shfl_xor_sync(0xffffffffu, s, off);
        float inv = 1.0f / sqrtf(s);
        __half* ar = g_A3 + (size_t)warp * KTOT;
        __half* br = g_B3 + (size_t)warp * KTOT;
        #pragma unroll
        for (int k = lane; k < DDIM; k += 32) {
            float fa = x[k];
            __half ha = __float2half(fa);
            __half la = __float2half(fa - __half2float(ha));
            ar[k] = ha; ar[DDIM + k] = ha; ar[2 * DDIM + k] = la;
            float fb = fa * inv;
            __half hb = __float2half(fb);
            __half lb = __float2half(fb - __half2float(hb));
            br[k] = hb; br[DDIM + k] = lb; br[2 * DDIM + k] = hb;
        }
    }
    int gt = blockIdx.x * blockDim.x + threadIdx.x;
    if (gt < NROWS) g_dv[gt] = 0;
}

// ---------------- kernel 2: HMMA GEMM-NT (mma.sync m16n8k16 f16->f32) ----------------
// 128x128 CTA tile, BK=32, 4-stage cp.async pipeline, 8 warps (32x64 warp tile).
#define BM 128
#define BN 128
#define BK 32
#define STAGES 4
#define KITER (KTOT / BK)          // 24
#define SSTRIDE 40                 // fp16 per smem row (32 data + 8 pad) -> conflict-free ldmatrix
#define STAGE_HALF (BM * SSTRIDE)  // 5120 fp16 per matrix per stage
#define STAGE_BYTES (2 * STAGE_HALF * 2)  // 20480
#define GEMM_SMEM (STAGES * STAGE_BYTES)  // 81920

__device__ __forceinline__ void ldsm_x4(uint32_t* r, uint32_t addr) {
    asm volatile("ldmatrix.sync.aligned.m8n8.x4.shared.b16 {%0,%1,%2,%3}, [%4];"
                 : "=r"(r[0]), "=r"(r[1]), "=r"(r[2]), "=r"(r[3]) : "r"(addr));
}
__device__ __forceinline__ void mma16816(float* c, const uint32_t* a, uint32_t b0, uint32_t b1) {
    asm volatile("mma.sync.aligned.m16n8k16.row.col.f32.f16.f16.f32 "
                 "{%0,%1,%2,%3}, {%4,%5,%6,%7}, {%8,%9}, {%0,%1,%2,%3};"
                 : "+f"(c[0]), "+f"(c[1]), "+f"(c[2]), "+f"(c[3])
                 : "r"(a[0]), "r"(a[1]), "r"(a[2]), "r"(a[3]), "r"(b0), "r"(b1));
}

__global__ __launch_bounds__(256, 2) void k_gemm() {
    extern __shared__ __half smem[];
    uint32_t sbase = smem_u32(smem);
    int tid = threadIdx.x, lane = tid & 31, wid = tid >> 5;
    int bm = blockIdx.y * BM, bn = blockIdx.x * BN;
    int wm0 = (wid >> 1) * 32;     // warp m offset (4 warps along m)
    int wn0 = (wid & 1) * 64;      // warp n offset (2 warps along n)

    // per-thread load slots: chunk c in [0,512): row=c>>2, 16B seg=c&3 (A and B identical)
    int r0 = tid >> 2, s0 = tid & 3;
    int r1 = (tid + 256) >> 2, s1 = (tid + 256) & 3;
    const __half* gA = g_A3 + (size_t)bm * KTOT;
    const __half* gB = g_B3 + (size_t)bn * KTOT;

    float acc[2][8][4];
    #pragma unroll
    for (int mt = 0; mt < 2; mt++)
        #pragma unroll
        for (int nt = 0; nt < 8; nt++)
            #pragma unroll
            for (int i = 0; i < 4; i++) acc[mt][nt][i] = 0.f;

    // prologue: stages 0..2
    #pragma unroll
    for (int s = 0; s < STAGES - 1; s++) {
        int k0 = s * BK;
        uint32_t sa = sbase + s * STAGE_BYTES;
        uint32_t sbm = sa + STAGE_HALF * 2;
        asm volatile("cp.async.cg.shared.global [%0], [%1], 16;" ::
                     "r"(sa + (r0 * SSTRIDE + s0 * 8) * 2), "l"(gA + (size_t)r0 * KTOT + k0 + s0 * 8));
        asm volatile("cp.async.cg.shared.global [%0], [%1], 16;" ::
                     "r"(sa + (r1 * SSTRIDE + s1 * 8) * 2), "l"(gA + (size_t)r1 * KTOT + k0 + s1 * 8));
        asm volatile("cp.async.cg.shared.global [%0], [%1], 16;" ::
                     "r"(sbm + (r0 * SSTRIDE + s0 * 8) * 2), "l"(gB + (size_t)r0 * KTOT + k0 + s0 * 8));
        asm volatile("cp.async.cg.shared.global [%0], [%1], 16;" ::
                     "r"(sbm + (r1 * SSTRIDE + s1 * 8) * 2), "l"(gB + (size_t)r1 * KTOT + k0 + s1 * 8));
        asm volatile("cp.async.commit_group;");
    }

    for (int i = 0; i < KITER; i++) {
        asm volatile("cp.async.wait_group %0;" :: "n"(STAGES - 2));
        __syncthreads();
        int st = i & (STAGES - 1);
        uint32_t As = sbase + st * STAGE_BYTES;
        uint32_t Bs = As + STAGE_HALF * 2;

        #pragma unroll
        for (int ks = 0; ks < 2; ks++) {
            uint32_t a[2][4];
            #pragma unroll
            for (int mt = 0; mt < 2; mt++)
                ldsm_x4(a[mt], As + ((wm0 + mt * 16 + (lane & 15)) * SSTRIDE + ks * 16 + (lane >> 4) * 8) * 2);
            #pragma unroll
            for (int ng = 0; ng < 4; ng++) {
                uint32_t b[4];
                ldsm_x4(b, Bs + ((wn0 + ng * 16 + (lane & 15)) * SSTRIDE + ks * 16 + (lane >> 4) * 8) * 2);
                #pragma unroll
                for (int mt = 0; mt < 2; mt++) {
                    mma16816(acc[mt][ng * 2 + 0], a[mt], b[0], b[2]);   // n8 rows 0-7
                    mma16816(acc[mt][ng * 2 + 1], a[mt], b[1], b[3]);   // n8 rows 8-15
                }
            }
        }

        int pf = i + STAGES - 1;
        if (pf < KITER) {
            int k0 = pf * BK;
            uint32_t sa = sbase + (pf & (STAGES - 1)) * STAGE_BYTES;
            uint32_t sbm = sa + STAGE_HALF * 2;
            asm volatile("cp.async.cg.shared.global [%0], [%1], 16;" ::
                         "r"(sa + (r0 * SSTRIDE + s0 * 8) * 2), "l"(gA + (size_t)r0 * KTOT + k0 + s0 * 8));
            asm volatile("cp.async.cg.shared.global [%0], [%1], 16;" ::
                         "r"(sa + (r1 * SSTRIDE + s1 * 8) * 2), "l"(gA + (size_t)r1 * KTOT + k0 + s1 * 8));
            asm volatile("cp.async.cg.shared.global [%0], [%1], 16;" ::
                         "r"(sbm + (r0 * SSTRIDE + s0 * 8) * 2), "l"(gB + (size_t)r0 * KTOT + k0 + s0 * 8));
            asm volatile("cp.async.cg.shared.global [%0], [%1], 16;" ::
                         "r"(sbm + (r1 * SSTRIDE + s1 * 8) * 2), "l"(gB + (size_t)r1 * KTOT + k0 + s1 * 8));
        }
        asm volatile("cp.async.commit_group;");
        __syncthreads();
    }

    // epilogue: c0,c1 -> (row, 2col), c2,c3 -> (row+8, 2col)
    int gid = lane >> 2, tig = lane & 3;
    #pragma unroll
    for (int mt = 0; mt < 2; mt++) {
        int row = bm + wm0 + mt * 16 + gid;
        #pragma unroll
        for (int nt = 0; nt < 8; nt++) {
            int col = bn + wn0 + nt * 8 + 2 * tig;
            float* p0 = g_sim + (size_t)row * NROWS + col;
            float* p1 = g_sim + (size_t)(row + 8) * NROWS + col;
            *(float2*)p0 = make_float2(acc[mt][nt][0], acc[mt][nt][1]);
            *(float2*)p1 = make_float2(acc[mt][nt][2], acc[mt][nt][3]);
        }
    }
}

// ---------------- kernel 3: per-row top-10, two-pass threshold ----------------
#define TCAP 512
__device__ __forceinline__ void topk_ins(float v, int j, float* bv, int* bi) {
    if (v > bv[KN - 1] || (v == bv[KN - 1] && j < bi[KN - 1])) {
        float cv = v; int ci = j;
        #pragma unroll
        for (int t = 0; t < KN; t++) {
            bool better = (cv > bv[t]) || (cv == bv[t] && ci < bi[t]);
            if (better) {
                float tv = bv[t]; int ti = bi[t];
                bv[t] = cv; bi[t] = ci;
                cv = tv; ci = ti;
            }
        }
    }
}

__global__ __launch_bounds__(128) void k_topk() {
    __shared__ float slv[4][TCAP];
    __shared__ int   sli[4][TCAP];
    __shared__ int   scnt[4];
    int w = threadIdx.x >> 5, lane = threadIdx.x & 31;
    int row = blockIdx.x * 4 + w;
    const float4* s4 = (const float4*)(g_sim + (size_t)row * NROWS);
    const float NEG_INF = __int_as_float(0xff800000);
    if (lane == 0) scnt[w] = 0;
    __syncwarp();

    // pass 1: per-lane max (branch-free)
    float lmax = NEG_INF;
    #pragma unroll 4
    for (int it = 0; it < NROWS / 128; it++) {
        float4 v = s4[it * 32 + lane];
        lmax = fmaxf(lmax, fmaxf(fmaxf(v.x, v.y), fmaxf(v.z, v.w)));
    }
    // theta = 10th largest of the 32 lane maxima -> 10 distinct elems >= theta,
    // hence true 10th value >= theta: all top-10 survive the filter.
    float val = lmax, theta = NEG_INF;
    #pragma unroll 1
    for (int r = 0; r < KN; r++) {
        float m = val;
        #pragma unroll
        for (int off = 16; off; off >>= 1) m = fmaxf(m, __shfl_xor_sync(0xffffffffu, m, off));
        theta = m;
        unsigned bmask = __ballot_sync(0xffffffffu, val == m);
        int leader = __ffs(bmask) - 1;
        if (lane == leader) val = NEG_INF;
    }

    // pass 2 (L2-hot): collect candidates v >= theta
    #pragma unroll 4
    for (int it = 0; it < NROWS / 128; it++) {
        int j4 = it * 32 + lane;
        float4 v = s4[j4];
        float m = fmaxf(fmaxf(v.x, v.y), fmaxf(v.z, v.w));
        if (m >= theta) {
            int jb = j4 * 4;
            if (v.x >= theta) { int p = atomicAdd(&scnt[w], 1); if (p < TCAP) { slv[w][p] = v.x; sli[w][p] = jb + 0; } }
            if (v.y >= theta) { int p = atomicAdd(&scnt[w], 1); if (p < TCAP) { slv[w][p] = v.y; sli[w][p] = jb + 1; } }
            if (v.z >= theta) { int p = atomicAdd(&scnt[w], 1); if (p < TCAP) { slv[w][p] = v.z; sli[w][p] = jb + 2; } }
            if (v.w >= theta) { int p = atomicAdd(&scnt[w], 1); if (p < TCAP) { slv[w][p] = v.w; sli[w][p] = jb + 3; } }
        }
    }
    __syncwarp();
    int cnt = scnt[w];

    float bv[KN]; int bi[KN];
    #pragma unroll
    for (int t = 0; t < KN; t++) { bv[t] = NEG_INF; bi[t] = 0x7fffffff; }

    if (cnt <= TCAP) {
        for (int i = lane; i < cnt; i += 32) topk_ins(slv[w][i], sli[w][i], bv, bi);
    } else {
        // exact fallback (never expected for continuous data)
        #pragma unroll 1
        for (int it = 0; it < NROWS / 128; it++) {
            int j4 = it * 32 + lane;
            float4 v = s4[j4];
            int jb = j4 * 4;
            topk_ins(v.x, jb + 0, bv, bi);
            topk_ins(v.y, jb + 1, bv, bi);
            topk_ins(v.z, jb + 2, bv, bi);
            topk_ins(v.w, jb + 3, bv, bi);
        }
    }

    // 10 rounds of warp argmax ((v desc, idx asc) comparator) with pop
    #pragma unroll 1
    for (int r = 0; r < KN; r++) {
        float mv = bv[0]; int mi = bi[0];
        #pragma unroll
        for (int off = 16; off; off >>= 1) {
            float ov = __shfl_xor_sync(0xffffffffu, mv, off);
            int   oi = __shfl_xor_sync(0xffffffffu, mi, off);
            if (ov > mv || (ov == mv && oi < mi)) { mv = ov; mi = oi; }
        }
        if (mi == bi[0]) {
            #pragma unroll
            for (int t = 0; t < KN - 1; t++) { bv[t] = bv[t + 1]; bi[t] = bi[t + 1]; }
            bv[KN - 1] = NEG_INF; bi[KN - 1] = 0x7fffffff;
        }
        if (lane == 0) {
            g_topk[row * KN + r] = mi;
            atomicAdd(&g_dv[mi], 1);
        }
    }
}

// ---------------- kernel 4: inv_dv ----------------
__global__ void k_invdv() {
    int i = blockIdx.x * blockDim.x + threadIdx.x;
    if (i < NROWS) {
        int d = g_dv[i];
        g_invdv[i] = d > 0 ? 1.0f / sqrtf((float)d) : 0.0f;
    }
}

// ---------------- kernel 5: zero the output ----------------
__global__ void k_zero(float4* __restrict__ out) {
    size_t i = (size_t)blockIdx.x * blockDim.x + threadIdx.x;
    size_t stride = (size_t)gridDim.x * blockDim.x;
    size_t n4 = (size_t)NROWS * NROWS / 4;
    for (; i < n4; i += stride) out[i] = make_float4(0.f, 0.f, 0.f, 0.f);
}

// ---------------- kernel 6: scatter 10x10 outer products per hyperedge ----------------
__global__ __launch_bounds__(128) void k_scatter(float* __restrict__ out) {
    __shared__ int   sidx[KN];
    __shared__ float sw[KN];
    int e = blockIdx.x;
    int t = threadIdx.x;
    if (t < KN) {
        int a = g_topk[e * KN + t];
        sidx[t] = a;
        sw[t] = g_invdv[a];
    }
    __syncthreads();
    if (t < KN * KN) {
        int a = sidx[t / KN];
        int b = sidx[t % KN];
        float val = (0.1f * sw[t / KN]) * sw[t % KN];
        atomicAdd(&out[(size_t)a * NROWS + b], val);
    }
}

// ---------------- launch ----------------
extern "C" void kernel_launch(void* const* d_in, const int* in_sizes, int n_in,
                              void* d_out, int out_size) {
    const float* feats = (const float*)d_in[0];
    float* out = (float*)d_out;

    k_prep<<<(NROWS * 32) / 256, 256>>>(feats);

    cudaFuncSetAttribute(k_gemm, cudaFuncAttributeMaxDynamicSharedMemorySize, GEMM_SMEM);
    k_gemm<<<dim3(NROWS / BN, NROWS / BM), 256, GEMM_SMEM>>>();

    k_zero<<<2048, 256>>>((float4*)out);

    k_topk<<<NROWS / 4, 128>>>();
    k_invdv<<<NROWS / 256, 256>>>();
    k_scatter<<<NROWS, 128>>>(out);
}

// round 7
// speedup vs baseline: 4.0679x; 1.6154x over previous
#include <cuda_runtime.h>
#include <cuda_fp16.h>
#include <cstdint>

#define NROWS 8192
#define DDIM  256
#define KN    10

// ---------------- scratch (static device globals; no allocation) ----------------
__device__ __half    g_Ah[(size_t)NROWS * DDIM];     // fp16(feats)
__device__ __half    g_Bh[(size_t)NROWS * DDIM];     // fp16(feats/||feats||)
__device__ float     g_invn[NROWS];                  // 1/||feats||
__device__ float     g_sim[(size_t)NROWS * NROWS];   // fp16-accurate scores
__device__ uint32_t  g_bmax[(size_t)NROWS * 64];     // per-128-col block maxima (monotone uint keys)
__device__ float     g_theta[NROWS];
__device__ int       g_topk[NROWS * KN];
__device__ int       g_dv[NROWS];
__device__ float     g_invdv[NROWS];

__device__ __forceinline__ uint32_t smem_u32(const void* p) {
    uint32_t a;
    asm("{ .reg .u64 t; cvta.to.shared.u64 t, %1; cvt.u32.u64 %0, t; }" : "=r"(a) : "l"(p));
    return a;
}
// monotone float->uint key (total order incl. negatives)
__device__ __forceinline__ uint32_t fkey(float f) {
    uint32_t u = __float_as_uint(f);
    return (u & 0x80000000u) ? ~u : (u | 0x80000000u);
}
__device__ __forceinline__ float fkeyinv(uint32_t k) {
    return (k & 0x80000000u) ? __uint_as_float(k ^ 0x80000000u) : __uint_as_float(~k);
}

// ---------------- kernel 1: prep — norms, fp16 casts; zero dv ----------------
__global__ __launch_bounds__(256) void k_prep(const float* __restrict__ feats) {
    int warp = (blockIdx.x * blockDim.x + threadIdx.x) >> 5;
    int lane = threadIdx.x & 31;
    if (warp < NROWS) {
        const float* x = feats + (size_t)warp * DDIM;
        float s = 0.f;
        #pragma unroll
        for (int k = lane; k < DDIM; k += 32) { float v = x[k]; s += v * v; }
        #pragma unroll
        for (int off = 16; off; off >>= 1) s += __shfl_xor_sync(0xffffffffu, s, off);
        float inv = 1.0f / sqrtf(s);
        if (lane == 0) g_invn[warp] = inv;
        __half* ar = g_Ah + (size_t)warp * DDIM;
        __half* br = g_Bh + (size_t)warp * DDIM;
        #pragma unroll
        for (int k = lane; k < DDIM; k += 32) {
            float fa = x[k];
            ar[k] = __float2half(fa);
            br[k] = __float2half(fa * inv);
        }
    }
    int gt = blockIdx.x * blockDim.x + threadIdx.x;
    if (gt < NROWS) g_dv[gt] = 0;
}

// ---------------- kernel 2: HMMA GEMM-NT fp16 K=256 + block-max epilogue ----------------
#define BM 128
#define BN 128
#define BK 32
#define STAGES 3
#define KITER (DDIM / BK)          // 8
#define SSTRIDE 40
#define STAGE_HALF (BM * SSTRIDE)
#define STAGE_BYTES (2 * STAGE_HALF * 2)
#define GEMM_SMEM (STAGES * STAGE_BYTES)   // 61440

__device__ __forceinline__ void ldsm_x4(uint32_t* r, uint32_t addr) {
    asm volatile("ldmatrix.sync.aligned.m8n8.x4.shared.b16 {%0,%1,%2,%3}, [%4];"
                 : "=r"(r[0]), "=r"(r[1]), "=r"(r[2]), "=r"(r[3]) : "r"(addr));
}
__device__ __forceinline__ void mma16816(float* c, const uint32_t* a, uint32_t b0, uint32_t b1) {
    asm volatile("mma.sync.aligned.m16n8k16.row.col.f32.f16.f16.f32 "
                 "{%0,%1,%2,%3}, {%4,%5,%6,%7}, {%8,%9}, {%0,%1,%2,%3};"
                 : "+f"(c[0]), "+f"(c[1]), "+f"(c[2]), "+f"(c[3])
                 : "r"(a[0]), "r"(a[1]), "r"(a[2]), "r"(a[3]), "r"(b0), "r"(b1));
}

__global__ __launch_bounds__(256, 2) void k_gemm() {
    extern __shared__ __half smem[];
    uint32_t sbase = smem_u32(smem);
    int tid = threadIdx.x, lane = tid & 31, wid = tid >> 5;
    int bm = blockIdx.y * BM, bn = blockIdx.x * BN;
    int wm0 = (wid >> 1) * 32;
    int wn0 = (wid & 1) * 64;

    int r0 = tid >> 2, s0 = tid & 3;
    int r1 = (tid + 256) >> 2, s1 = (tid + 256) & 3;
    const __half* gA = g_Ah + (size_t)bm * DDIM;
    const __half* gB = g_Bh + (size_t)bn * DDIM;

    float acc[2][8][4];
    #pragma unroll
    for (int mt = 0; mt < 2; mt++)
        #pragma unroll
        for (int nt = 0; nt < 8; nt++)
            #pragma unroll
            for (int i = 0; i < 4; i++) acc[mt][nt][i] = 0.f;

    #pragma unroll
    for (int s = 0; s < STAGES - 1; s++) {
        int k0 = s * BK;
        uint32_t sa = sbase + s * STAGE_BYTES;
        uint32_t sbm = sa + STAGE_HALF * 2;
        asm volatile("cp.async.cg.shared.global [%0], [%1], 16;" ::
                     "r"(sa + (r0 * SSTRIDE + s0 * 8) * 2), "l"(gA + (size_t)r0 * DDIM + k0 + s0 * 8));
        asm volatile("cp.async.cg.shared.global [%0], [%1], 16;" ::
                     "r"(sa + (r1 * SSTRIDE + s1 * 8) * 2), "l"(gA + (size_t)r1 * DDIM + k0 + s1 * 8));
        asm volatile("cp.async.cg.shared.global [%0], [%1], 16;" ::
                     "r"(sbm + (r0 * SSTRIDE + s0 * 8) * 2), "l"(gB + (size_t)r0 * DDIM + k0 + s0 * 8));
        asm volatile("cp.async.cg.shared.global [%0], [%1], 16;" ::
                     "r"(sbm + (r1 * SSTRIDE + s1 * 8) * 2), "l"(gB + (size_t)r1 * DDIM + k0 + s1 * 8));
        asm volatile("cp.async.commit_group;");
    }

    for (int i = 0; i < KITER; i++) {
        asm volatile("cp.async.wait_group %0;" :: "n"(STAGES - 2));
        __syncthreads();
        int st = i % STAGES;
        uint32_t As = sbase + st * STAGE_BYTES;
        uint32_t Bs = As + STAGE_HALF * 2;

        #pragma unroll
        for (int ks = 0; ks < 2; ks++) {
            uint32_t a[2][4];
            #pragma unroll
            for (int mt = 0; mt < 2; mt++)
                ldsm_x4(a[mt], As + ((wm0 + mt * 16 + (lane & 15)) * SSTRIDE + ks * 16 + (lane >> 4) * 8) * 2);
            #pragma unroll
            for (int ng = 0; ng < 4; ng++) {
                uint32_t b[4];
                ldsm_x4(b, Bs + ((wn0 + ng * 16 + (lane & 15)) * SSTRIDE + ks * 16 + (lane >> 4) * 8) * 2);
                #pragma unroll
                for (int mt = 0; mt < 2; mt++) {
                    mma16816(acc[mt][ng * 2 + 0], a[mt], b[0], b[2]);
                    mma16816(acc[mt][ng * 2 + 1], a[mt], b[1], b[3]);
                }
            }
        }

        int pf = i + STAGES - 1;
        if (pf < KITER) {
            int k0 = pf * BK;
            uint32_t sa = sbase + (pf % STAGES) * STAGE_BYTES;
            uint32_t sbm = sa + STAGE_HALF * 2;
            asm volatile("cp.async.cg.shared.global [%0], [%1], 16;" ::
                         "r"(sa + (r0 * SSTRIDE + s0 * 8) * 2), "l"(gA + (size_t)r0 * DDIM + k0 + s0 * 8));
            asm volatile("cp.async.cg.shared.global [%0], [%1], 16;" ::
                         "r"(sa + (r1 * SSTRIDE + s1 * 8) * 2), "l"(gA + (size_t)r1 * DDIM + k0 + s1 * 8));
            asm volatile("cp.async.cg.shared.global [%0], [%1], 16;" ::
                         "r"(sbm + (r0 * SSTRIDE + s0 * 8) * 2), "l"(gB + (size_t)r0 * DDIM + k0 + s0 * 8));
            asm volatile("cp.async.cg.shared.global [%0], [%1], 16;" ::
                         "r"(sbm + (r1 * SSTRIDE + s1 * 8) * 2), "l"(gB + (size_t)r1 * DDIM + k0 + s1 * 8));
        }
        asm volatile("cp.async.commit_group;");
        __syncthreads();
    }

    // sim store: c0,c1 -> (row, col..col+1), c2,c3 -> (row+8, ...)
    int gid = lane >> 2, tig = lane & 3;
    #pragma unroll
    for (int mt = 0; mt < 2; mt++) {
        int row = bm + wm0 + mt * 16 + gid;
        #pragma unroll
        for (int nt = 0; nt < 8; nt++) {
            int col = bn + wn0 + nt * 8 + 2 * tig;
            *(float2*)(g_sim + (size_t)row * NROWS + col) = make_float2(acc[mt][nt][0], acc[mt][nt][1]);
            *(float2*)(g_sim + (size_t)(row + 8) * NROWS + col) = make_float2(acc[mt][nt][2], acc[mt][nt][3]);
        }
    }

    // block-max epilogue: per-row max over this CTA's 128 cols -> g_bmax[row][bx]
    asm volatile("cp.async.wait_group 0;" ::);
    __syncthreads();
    uint32_t* smax = (uint32_t*)smem;   // [128][2]
    if (tid < 256) smax[tid] = 0;
    __syncthreads();
    const float NEG_INF = __int_as_float(0xff800000);
    #pragma unroll
    for (int mt = 0; mt < 2; mt++) {
        #pragma unroll
        for (int h = 0; h < 2; h++) {   // c pair: {0,1} row, {2,3} row+8
            float mx = NEG_INF;
            #pragma unroll
            for (int nt = 0; nt < 8; nt++)
                mx = fmaxf(mx, fmaxf(acc[mt][nt][h * 2 + 0], acc[mt][nt][h * 2 + 1]));
            mx = fmaxf(mx, __shfl_xor_sync(0xffffffffu, mx, 1));
            mx = fmaxf(mx, __shfl_xor_sync(0xffffffffu, mx, 2));
            if (tig == 0)
                smax[(wm0 + mt * 16 + h * 8 + gid) * 2 + (wid & 1)] = fkey(mx);
        }
    }
    __syncthreads();
    if (tid < 128) {
        uint32_t k = max(smax[tid * 2], smax[tid * 2 + 1]);
        g_bmax[(size_t)(bm + tid) * 64 + blockIdx.x] = k;
    }
}

// ---------------- kernel 3: theta = 20th largest of 64 block maxima ----------------
__global__ __launch_bounds__(256) void k_theta() {
    int row = blockIdx.x * 8 + (threadIdx.x >> 5);
    int lane = threadIdx.x & 31;
    const uint32_t* bk = g_bmax + (size_t)row * 64;
    uint32_t v0 = bk[lane], v1 = bk[lane + 32];
    uint32_t M = 0;
    #pragma unroll 1
    for (int r = 0; r < 20; r++) {
        uint32_t lm = max(v0, v1);
        M = lm;
        #pragma unroll
        for (int off = 16; off; off >>= 1) M = max(M, __shfl_xor_sync(0xffffffffu, M, off));
        unsigned b = __ballot_sync(0xffffffffu, lm == M);
        if (lane == __ffs(b) - 1) { if (v0 == M) v0 = 0; else v1 = 0; }
    }
    if (lane == 0) g_theta[row] = fkeyinv(M);
}

// ---------------- kernel 4: single-pass candidates + exact rescore + exact top-10 ----------------
#define TCAP 512
__device__ __forceinline__ void topk_ins(float v, int j, float* bv, int* bi) {
    if (v > bv[KN - 1] || (v == bv[KN - 1] && j < bi[KN - 1])) {
        float cv = v; int ci = j;
        #pragma unroll
        for (int t = 0; t < KN; t++) {
            bool better = (cv > bv[t]) || (cv == bv[t] && ci < bi[t]);
            if (better) {
                float tv = bv[t]; int ti = bi[t];
                bv[t] = cv; bi[t] = ci;
                cv = tv; ci = ti;
            }
        }
    }
}

__global__ __launch_bounds__(128) void k_topk(const float* __restrict__ feats) {
    __shared__ float slv[4][TCAP];
    __shared__ int   sli[4][TCAP];
    __shared__ int   scnt[4];
    int w = threadIdx.x >> 5, lane = threadIdx.x & 31;
    int row = blockIdx.x * 4 + w;
    const float4* s4 = (const float4*)(g_sim + (size_t)row * NROWS);
    const float NEG_INF = __int_as_float(0xff800000);
    float theta = g_theta[row];
    if (lane == 0) scnt[w] = 0;
    __syncwarp();

    // single streaming pass: collect approx >= theta (guaranteed to contain true top-10)
    #pragma unroll 1
    for (int o = 0; o < 8; o++) {
        float4 v[8];
        #pragma unroll
        for (int u = 0; u < 8; u++) v[u] = s4[o * 256 + u * 32 + lane];
        #pragma unroll
        for (int u = 0; u < 8; u++) {
            float m = fmaxf(fmaxf(v[u].x, v[u].y), fmaxf(v[u].z, v[u].w));
            if (m >= theta) {
                int jb = (o * 256 + u * 32 + lane) * 4;
                if (v[u].x >= theta) { int p = atomicAdd(&scnt[w], 1); if (p < TCAP) { sli[w][p] = jb + 0; } }
                if (v[u].y >= theta) { int p = atomicAdd(&scnt[w], 1); if (p < TCAP) { sli[w][p] = jb + 1; } }
                if (v[u].z >= theta) { int p = atomicAdd(&scnt[w], 1); if (p < TCAP) { sli[w][p] = jb + 2; } }
                if (v[u].w >= theta) { int p = atomicAdd(&scnt[w], 1); if (p < TCAP) { sli[w][p] = jb + 3; } }
            }
        }
    }
    __syncwarp();
    int cnt = min(scnt[w], TCAP);

    // exact fp32 rescore of candidates: sim = dot(feats_row, feats_j) * invn_j
    const float4* fr = (const float4*)(feats + (size_t)row * DDIM);
    for (int i = lane; i < cnt; i += 32) {
        int j = sli[w][i];
        const float4* fj = (const float4*)(feats + (size_t)j * DDIM);
        float s = 0.f;
        #pragma unroll 8
        for (int k = 0; k < DDIM / 4; k++) {
            float4 a = fr[k], b = fj[k];
            s += a.x * b.x + a.y * b.y + a.z * b.z + a.w * b.w;
        }
        slv[w][i] = s * g_invn[j];
    }
    __syncwarp();

    // exact top-10 over candidates
    float bv[KN]; int bi[KN];
    #pragma unroll
    for (int t = 0; t < KN; t++) { bv[t] = NEG_INF; bi[t] = 0x7fffffff; }
    for (int i = lane; i < cnt; i += 32) topk_ins(slv[w][i], sli[w][i], bv, bi);

    #pragma unroll 1
    for (int r = 0; r < KN; r++) {
        float mv = bv[0]; int mi = bi[0];
        #pragma unroll
        for (int off = 16; off; off >>= 1) {
            float ov = __shfl_xor_sync(0xffffffffu, mv, off);
            int   oi = __shfl_xor_sync(0xffffffffu, mi, off);
            if (ov > mv || (ov == mv && oi < mi)) { mv = ov; mi = oi; }
        }
        if (mi == bi[0]) {
            #pragma unroll
            for (int t = 0; t < KN - 1; t++) { bv[t] = bv[t + 1]; bi[t] = bi[t + 1]; }
            bv[KN - 1] = NEG_INF; bi[KN - 1] = 0x7fffffff;
        }
        if (lane == 0) {
            g_topk[row * KN + r] = mi;
            atomicAdd(&g_dv[mi], 1);
        }
    }
}

// ---------------- kernel 5: inv_dv ----------------
__global__ void k_invdv() {
    int i = blockIdx.x * blockDim.x + threadIdx.x;
    if (i < NROWS) {
        int d = g_dv[i];
        g_invdv[i] = d > 0 ? 1.0f / sqrtf((float)d) : 0.0f;
    }
}

// ---------------- kernel 6: zero the output ----------------
__global__ void k_zero(float4* __restrict__ out) {
    size_t i = (size_t)blockIdx.x * blockDim.x + threadIdx.x;
    size_t stride = (size_t)gridDim.x * blockDim.x;
    size_t n4 = (size_t)NROWS * NROWS / 4;
    for (; i < n4; i += stride) out[i] = make_float4(0.f, 0.f, 0.f, 0.f);
}

// ---------------- kernel 7: scatter 10x10 outer products per hyperedge ----------------
__global__ __launch_bounds__(128) void k_scatter(float* __restrict__ out) {
    __shared__ int   sidx[KN];
    __shared__ float sw[KN];
    int e = blockIdx.x;
    int t = threadIdx.x;
    if (t < KN) {
        int a = g_topk[e * KN + t];
        sidx[t] = a;
        sw[t] = g_invdv[a];
    }
    __syncthreads();
    if (t < KN * KN) {
        int a = sidx[t / KN];
        int b = sidx[t % KN];
        float val = (0.1f * sw[t / KN]) * sw[t % KN];
        atomicAdd(&out[(size_t)a * NROWS + b], val);
    }
}

// ---------------- launch ----------------
extern "C" void kernel_launch(void* const* d_in, const int* in_sizes, int n_in,
                              void* d_out, int out_size) {
    const float* feats = (const float*)d_in[0];
    float* out = (float*)d_out;

    k_prep<<<(NROWS * 32) / 256, 256>>>(feats);

    cudaFuncSetAttribute(k_gemm, cudaFuncAttributeMaxDynamicSharedMemorySize, GEMM_SMEM);
    k_gemm<<<dim3(NROWS / BN, NROWS / BM), 256, GEMM_SMEM>>>();

    k_zero<<<2048, 256>>>((float4*)out);

    k_theta<<<NROWS / 8, 256>>>();
    k_topk<<<NROWS / 4, 128>>>(feats);
    k_invdv<<<NROWS / 256, 256>>>();
    k_scatter<<<NROWS, 128>>>(out);
}

// round 9
// speedup vs baseline: 4.5619x; 1.1214x over previous
#include <cuda_runtime.h>
#include <cuda_fp16.h>
#include <cstdint>

#define NROWS 8192
#define DDIM  256
#define KN    10

// ---------------- scratch (static device globals; no allocation) ----------------
__device__ __half    g_Ah[(size_t)NROWS * DDIM];     // fp16(feats)
__device__ __half    g_Bh[(size_t)NROWS * DDIM];     // fp16(feats/||feats||)
__device__ float     g_invn[NROWS];                  // 1/||feats||
__device__ __half    g_simh[(size_t)NROWS * NROWS];  // fp16 approx scores (128 MB)
__device__ uint32_t  g_bmax[(size_t)NROWS * 64];     // per-128-col block maxima (monotone keys, of the STORED halves)
__device__ float     g_theta[NROWS];
__device__ int       g_topk[NROWS * KN];
__device__ int       g_dv[NROWS];
__device__ float     g_invdv[NROWS];

__device__ __forceinline__ uint32_t smem_u32(const void* p) {
    uint32_t a;
    asm("{ .reg .u64 t; cvta.to.shared.u64 t, %1; cvt.u32.u64 %0, t; }" : "=r"(a) : "l"(p));
    return a;
}
// monotone float->uint key (total order incl. negatives)
__device__ __forceinline__ uint32_t fkey(float f) {
    uint32_t u = __float_as_uint(f);
    return (u & 0x80000000u) ? ~u : (u | 0x80000000u);
}
__device__ __forceinline__ float fkeyinv(uint32_t k) {
    return (k & 0x80000000u) ? __uint_as_float(k ^ 0x80000000u) : __uint_as_float(~k);
}

// ---------------- kernel 1: prep — norms, fp16 casts; zero dv ----------------
__global__ __launch_bounds__(256) void k_prep(const float* __restrict__ feats) {
    int warp = (blockIdx.x * blockDim.x + threadIdx.x) >> 5;
    int lane = threadIdx.x & 31;
    if (warp < NROWS) {
        const float* x = feats + (size_t)warp * DDIM;
        float s = 0.f;
        #pragma unroll
        for (int k = lane; k < DDIM; k += 32) { float v = x[k]; s += v * v; }
        #pragma unroll
        for (int off = 16; off; off >>= 1) s += __shfl_xor_sync(0xffffffffu, s, off);
        float inv = 1.0f / sqrtf(s);
        if (lane == 0) g_invn[warp] = inv;
        __half* ar = g_Ah + (size_t)warp * DDIM;
        __half* br = g_Bh + (size_t)warp * DDIM;
        #pragma unroll
        for (int k = lane; k < DDIM; k += 32) {
            float fa = x[k];
            ar[k] = __float2half(fa);
            br[k] = __float2half(fa * inv);
        }
    }
    int gt = blockIdx.x * blockDim.x + threadIdx.x;
    if (gt < NROWS) g_dv[gt] = 0;
}

// ---------------- kernel 2: HMMA GEMM-NT fp16 K=256, half sim store, block-max epilogue,
//                  + folded zeroing of the output (hidden behind tensor work) ----------------
#define BM 128
#define BN 128
#define BK 32
#define STAGES 3
#define KITER (DDIM / BK)          // 8
#define SSTRIDE 40
#define STAGE_HALF (BM * SSTRIDE)
#define STAGE_BYTES (2 * STAGE_HALF * 2)
#define GEMM_SMEM (STAGES * STAGE_BYTES)   // 61440

__device__ __forceinline__ void ldsm_x4(uint32_t* r, uint32_t addr) {
    asm volatile("ldmatrix.sync.aligned.m8n8.x4.shared.b16 {%0,%1,%2,%3}, [%4];"
                 : "=r"(r[0]), "=r"(r[1]), "=r"(r[2]), "=r"(r[3]) : "r"(addr));
}
__device__ __forceinline__ void mma16816(float* c, const uint32_t* a, uint32_t b0, uint32_t b1) {
    asm volatile("mma.sync.aligned.m16n8k16.row.col.f32.f16.f16.f32 "
                 "{%0,%1,%2,%3}, {%4,%5,%6,%7}, {%8,%9}, {%0,%1,%2,%3};"
                 : "+f"(c[0]), "+f"(c[1]), "+f"(c[2]), "+f"(c[3])
                 : "r"(a[0]), "r"(a[1]), "r"(a[2]), "r"(a[3]), "r"(b0), "r"(b1));
}

__global__ __launch_bounds__(256, 2) void k_gemm(float4* __restrict__ out4) {
    extern __shared__ __half smem[];
    uint32_t sbase = smem_u32(smem);
    int tid = threadIdx.x, lane = tid & 31, wid = tid >> 5;
    int bm = blockIdx.y * BM, bn = blockIdx.x * BN;
    int wm0 = (wid >> 1) * 32;
    int wn0 = (wid & 1) * 64;

    // folded output zeroing: this CTA's 64KB slice (16 float4/thread), issued up
    // front so the DRAM writes drain while the MMA mainloop runs.
    {
        int cta = blockIdx.y * gridDim.x + blockIdx.x;          // 0..4095
        float4 z = make_float4(0.f, 0.f, 0.f, 0.f);
        size_t base = (size_t)cta * 4096 + tid;
        #pragma unroll
        for (int i = 0; i < 16; i++) out4[base + i * 256] = z;
    }

    int r0 = tid >> 2, s0 = tid & 3;
    int r1 = (tid + 256) >> 2, s1 = (tid + 256) & 3;
    const __half* gA = g_Ah + (size_t)bm * DDIM;
    const __half* gB = g_Bh + (size_t)bn * DDIM;

    float acc[2][8][4];
    #pragma unroll
    for (int mt = 0; mt < 2; mt++)
        #pragma unroll
        for (int nt = 0; nt < 8; nt++)
            #pragma unroll
            for (int i = 0; i < 4; i++) acc[mt][nt][i] = 0.f;

    #pragma unroll
    for (int s = 0; s < STAGES - 1; s++) {
        int k0 = s * BK;
        uint32_t sa = sbase + s * STAGE_BYTES;
        uint32_t sbm = sa + STAGE_HALF * 2;
        asm volatile("cp.async.cg.shared.global [%0], [%1], 16;" ::
                     "r"(sa + (r0 * SSTRIDE + s0 * 8) * 2), "l"(gA + (size_t)r0 * DDIM + k0 + s0 * 8));
        asm volatile("cp.async.cg.shared.global [%0], [%1], 16;" ::
                     "r"(sa + (r1 * SSTRIDE + s1 * 8) * 2), "l"(gA + (size_t)r1 * DDIM + k0 + s1 * 8));
        asm volatile("cp.async.cg.shared.global [%0], [%1], 16;" ::
                     "r"(sbm + (r0 * SSTRIDE + s0 * 8) * 2), "l"(gB + (size_t)r0 * DDIM + k0 + s0 * 8));
        asm volatile("cp.async.cg.shared.global [%0], [%1], 16;" ::
                     "r"(sbm + (r1 * SSTRIDE + s1 * 8) * 2), "l"(gB + (size_t)r1 * DDIM + k0 + s1 * 8));
        asm volatile("cp.async.commit_group;");
    }

    for (int i = 0; i < KITER; i++) {
        asm volatile("cp.async.wait_group %0;" :: "n"(STAGES - 2));
        __syncthreads();
        int st = i % STAGES;
        uint32_t As = sbase + st * STAGE_BYTES;
        uint32_t Bs = As + STAGE_HALF * 2;

        #pragma unroll
        for (int ks = 0; ks < 2; ks++) {
            uint32_t a[2][4];
            #pragma unroll
            for (int mt = 0; mt < 2; mt++)
                ldsm_x4(a[mt], As + ((wm0 + mt * 16 + (lane & 15)) * SSTRIDE + ks * 16 + (lane >> 4) * 8) * 2);
            #pragma unroll
            for (int ng = 0; ng < 4; ng++) {
                uint32_t b[4];
                ldsm_x4(b, Bs + ((wn0 + ng * 16 + (lane & 15)) * SSTRIDE + ks * 16 + (lane >> 4) * 8) * 2);
                #pragma unroll
                for (int mt = 0; mt < 2; mt++) {
                    mma16816(acc[mt][ng * 2 + 0], a[mt], b[0], b[2]);
                    mma16816(acc[mt][ng * 2 + 1], a[mt], b[1], b[3]);
                }
            }
        }

        int pf = i + STAGES - 1;
        if (pf < KITER) {
            int k0 = pf * BK;
            uint32_t sa = sbase + (pf % STAGES) * STAGE_BYTES;
            uint32_t sbm = sa + STAGE_HALF * 2;
            asm volatile("cp.async.cg.shared.global [%0], [%1], 16;" ::
                         "r"(sa + (r0 * SSTRIDE + s0 * 8) * 2), "l"(gA + (size_t)r0 * DDIM + k0 + s0 * 8));
            asm volatile("cp.async.cg.shared.global [%0], [%1], 16;" ::
                         "r"(sa + (r1 * SSTRIDE + s1 * 8) * 2), "l"(gA + (size_t)r1 * DDIM + k0 + s1 * 8));
            asm volatile("cp.async.cg.shared.global [%0], [%1], 16;" ::
                         "r"(sbm + (r0 * SSTRIDE + s0 * 8) * 2), "l"(gB + (size_t)r0 * DDIM + k0 + s0 * 8));
            asm volatile("cp.async.cg.shared.global [%0], [%1], 16;" ::
                         "r"(sbm + (r1 * SSTRIDE + s1 * 8) * 2), "l"(gB + (size_t)r1 * DDIM + k0 + s1 * 8));
        }
        asm volatile("cp.async.commit_group;");
        __syncthreads();
    }

    // epilogue: convert to half, store, and block-max over the STORED (rounded) values
    asm volatile("cp.async.wait_group 0;" ::);
    __syncthreads();
    uint32_t* smax = (uint32_t*)smem;   // [128][2]
    if (tid < 256) smax[tid] = 0;
    __syncthreads();

    const float NEG_INF = __int_as_float(0xff800000);
    int gid = lane >> 2, tig = lane & 3;
    #pragma unroll
    for (int mt = 0; mt < 2; mt++) {
        int row = bm + wm0 + mt * 16 + gid;
        float mx0 = NEG_INF, mx1 = NEG_INF;
        #pragma unroll
        for (int nt = 0; nt < 8; nt++) {
            int col = bn + wn0 + nt * 8 + 2 * tig;
            __half2 h0 = __floats2half2_rn(acc[mt][nt][0], acc[mt][nt][1]);
            __half2 h1 = __floats2half2_rn(acc[mt][nt][2], acc[mt][nt][3]);
            *(__half2*)(g_simh + (size_t)row * NROWS + col) = h0;
            *(__half2*)(g_simh + (size_t)(row + 8) * NROWS + col) = h1;
            float2 f0 = __half22float2(h0), f1 = __half22float2(h1);
            mx0 = fmaxf(mx0, fmaxf(f0.x, f0.y));
            mx1 = fmaxf(mx1, fmaxf(f1.x, f1.y));
        }
        mx0 = fmaxf(mx0, __shfl_xor_sync(0xffffffffu, mx0, 1));
        mx0 = fmaxf(mx0, __shfl_xor_sync(0xffffffffu, mx0, 2));
        mx1 = fmaxf(mx1, __shfl_xor_sync(0xffffffffu, mx1, 1));
        mx1 = fmaxf(mx1, __shfl_xor_sync(0xffffffffu, mx1, 2));
        if (tig == 0) {
            smax[(wm0 + mt * 16 + gid) * 2 + (wid & 1)] = fkey(mx0);
            smax[(wm0 + mt * 16 + 8 + gid) * 2 + (wid & 1)] = fkey(mx1);
        }
    }
    __syncthreads();
    if (tid < 128) {
        uint32_t k = max(smax[tid * 2], smax[tid * 2 + 1]);
        g_bmax[(size_t)(bm + tid) * 64 + blockIdx.x] = k;
    }
}

// ---------------- kernel 3: theta = 20th largest of 64 block maxima ----------------
__global__ __launch_bounds__(256) void k_theta() {
    int row = blockIdx.x * 8 + (threadIdx.x >> 5);
    int lane = threadIdx.x & 31;
    const uint32_t* bk = g_bmax + (size_t)row * 64;
    uint32_t v0 = bk[lane], v1 = bk[lane + 32];
    uint32_t M = 0;
    #pragma unroll 1
    for (int r = 0; r < 20; r++) {
        uint32_t lm = max(v0, v1);
        M = lm;
        #pragma unroll
        for (int off = 16; off; off >>= 1) M = max(M, __shfl_xor_sync(0xffffffffu, M, off));
        unsigned b = __ballot_sync(0xffffffffu, lm == M);
        if (lane == __ffs(b) - 1) { if (v0 == M) v0 = 0; else v1 = 0; }
    }
    if (lane == 0) g_theta[row] = fkeyinv(M);
}

// ---------------- kernel 4: single-pass candidates (half) + exact rescore + exact top-10 ----------------
#define TCAP 512
__device__ __forceinline__ void topk_ins(float v, int j, float* bv, int* bi) {
    if (v > bv[KN - 1] || (v == bv[KN - 1] && j < bi[KN - 1])) {
        float cv = v; int ci = j;
        #pragma unroll
        for (int t = 0; t < KN; t++) {
            bool better = (cv > bv[t]) || (cv == bv[t] && ci < bi[t]);
            if (better) {
                float tv = bv[t]; int ti = bi[t];
                bv[t] = cv; bi[t] = ci;
                cv = tv; ci = ti;
            }
        }
    }
}

__global__ __launch_bounds__(128) void k_topk(const float* __restrict__ feats) {
    __shared__ float slv[4][TCAP];
    __shared__ int   sli[4][TCAP];
    __shared__ int   scnt[4];
    int w = threadIdx.x >> 5, lane = threadIdx.x & 31;
    int row = blockIdx.x * 4 + w;
    const uint4* s8 = (const uint4*)(g_simh + (size_t)row * NROWS);   // 8 halves / load
    const float NEG_INF = __int_as_float(0xff800000);
    float theta = g_theta[row];           // exactly a stored half value
    __half th = __float2half_rn(theta);   // exact
    if (lane == 0) scnt[w] = 0;
    __syncwarp();

    // single streaming pass over half sim: collect approx >= theta
    #pragma unroll 1
    for (int o = 0; o < 8; o++) {
        uint4 q[4];
        #pragma unroll
        for (int u = 0; u < 4; u++) q[u] = s8[o * 128 + u * 32 + lane];
        #pragma unroll
        for (int u = 0; u < 4; u++) {
            __half2 p0 = *(__half2*)&q[u].x, p1 = *(__half2*)&q[u].y;
            __half2 p2 = *(__half2*)&q[u].z, p3 = *(__half2*)&q[u].w;
            __half2 m2 = __hmax2(__hmax2(p0, p1), __hmax2(p2, p3));
            if (__hge(__hmax(__low2half(m2), __high2half(m2)), th)) {
                int jb = (o * 128 + u * 32 + lane) * 8;
                const __half2 ps[4] = {p0, p1, p2, p3};
                #pragma unroll
                for (int e = 0; e < 4; e++) {
                    float2 f = __half22float2(ps[e]);
                    if (f.x >= theta) { int p = atomicAdd(&scnt[w], 1); if (p < TCAP) sli[w][p] = jb + e * 2 + 0; }
                    if (f.y >= theta) { int p = atomicAdd(&scnt[w], 1); if (p < TCAP) sli[w][p] = jb + e * 2 + 1; }
                }
            }
        }
    }
    __syncwarp();
    int cnt = scnt[w];

    float bv[KN]; int bi[KN];
    #pragma unroll
    for (int t = 0; t < KN; t++) { bv[t] = NEG_INF; bi[t] = 0x7fffffff; }

    const float4* fr = (const float4*)(feats + (size_t)row * DDIM);
    if (cnt <= TCAP) {
        // exact fp32 rescore of candidates: sim = dot(feats_row, feats_j) * invn_j
        for (int i = lane; i < cnt; i += 32) {
            int j = sli[w][i];
            const float4* fj = (const float4*)(feats + (size_t)j * DDIM);
            float s = 0.f;
            #pragma unroll 8
            for (int k = 0; k < DDIM / 4; k++) {
                float4 a = fr[k], b = fj[k];
                s += a.x * b.x + a.y * b.y + a.z * b.z + a.w * b.w;
            }
            slv[w][i] = s * g_invn[j];
        }
        __syncwarp();
        for (int i = lane; i < cnt; i += 32) topk_ins(slv[w][i], sli[w][i], bv, bi);
    } else {
        // exact fallback (never expected): full exact rescore of the row
        for (int j = lane; j < NROWS; j += 32) {
            const float4* fj = (const float4*)(feats + (size_t)j * DDIM);
            float s = 0.f;
            #pragma unroll 8
            for (int k = 0; k < DDIM / 4; k++) {
                float4 a = fr[k], b = fj[k];
                s += a.x * b.x + a.y * b.y + a.z * b.z + a.w * b.w;
            }
            topk_ins(s * g_invn[j], j, bv, bi);
        }
    }

    // 10 rounds of warp argmax ((v desc, idx asc) comparator) with pop
    #pragma unroll 1
    for (int r = 0; r < KN; r++) {
        float mv = bv[0]; int mi = bi[0];
        #pragma unroll
        for (int off = 16; off; off >>= 1) {
            float ov = __shfl_xor_sync(0xffffffffu, mv, off);
            int   oi = __shfl_xor_sync(0xffffffffu, mi, off);
            if (ov > mv || (ov == mv && oi < mi)) { mv = ov; mi = oi; }
        }
        if (mi == bi[0]) {
            #pragma unroll
            for (int t = 0; t < KN - 1; t++) { bv[t] = bv[t + 1]; bi[t] = bi[t + 1]; }
            bv[KN - 1] = NEG_INF; bi[KN - 1] = 0x7fffffff;
        }
        if (lane == 0) {
            g_topk[row * KN + r] = mi;
            atomicAdd(&g_dv[mi], 1);
        }
    }
}

// ---------------- kernel 5: inv_dv ----------------
__global__ void k_invdv() {
    int i = blockIdx.x * blockDim.x + threadIdx.x;
    if (i < NROWS) {
        int d = g_dv[i];
        g_invdv[i] = d > 0 ? 1.0f / sqrtf((float)d) : 0.0f;
    }
}

// ---------------- kernel 6: scatter 10x10 outer products per hyperedge ----------------
__global__ __launch_bounds__(128) void k_scatter(float* __restrict__ out) {
    __shared__ int   sidx[KN];
    __shared__ float sw[KN];
    int e = blockIdx.x;
    int t = threadIdx.x;
    if (t < KN) {
        int a = g_topk[e * KN + t];
        sidx[t] = a;
        sw[t] = g_invdv[a];
    }
    __syncthreads();
    if (t < KN * KN) {
        int a = sidx[t / KN];
        int b = sidx[t % KN];
        float val = (0.1f * sw[t / KN]) * sw[t % KN];
        atomicAdd(&out[(size_t)a * NROWS + b], val);
    }
}

// ---------------- launch ----------------
extern "C" void kernel_launch(void* const* d_in, const int* in_sizes, int n_in,
                              void* d_out, int out_size) {
    const float* feats = (const float*)d_in[0];
    float* out = (float*)d_out;

    k_prep<<<(NROWS * 32) / 256, 256>>>(feats);

    cudaFuncSetAttribute(k_gemm, cudaFuncAttributeMaxDynamicSharedMemorySize, GEMM_SMEM);
    k_gemm<<<dim3(NROWS / BN, NROWS / BM), 256, GEMM_SMEM>>>((float4*)out);

    k_theta<<<NROWS / 8, 256>>>();
    k_topk<<<NROWS / 4, 128>>>(feats);
    k_invdv<<<NROWS / 256, 256>>>();
    k_scatter<<<NROWS, 128>>>(out);
}

// round 10
// speedup vs baseline: 5.2106x; 1.1422x over previous
#include <cuda_runtime.h>
#include <cuda_fp16.h>
#include <cstdint>

#define NROWS 8192
#define DDIM  256
#define KN    10
#define NTB   64                   // 128-col blocks per row

// ---------------- scratch (static device globals; no allocation) ----------------
__device__ __half    g_Bh[(size_t)NROWS * DDIM];     // fp16(feats/||feats||)
__device__ float     g_invn[NROWS];                  // 1/||feats||
__device__ __half    g_simh[(size_t)NROWS * NROWS];  // fp16 cos (symmetric, 128 MB)
__device__ uint32_t  g_bmax[(size_t)NROWS * NTB];    // per-128-col block maxima (monotone keys of STORED halves)
__device__ float     g_theta[NROWS];
__device__ unsigned long long g_bmask[NROWS];        // blocks with bmax >= theta
__device__ int       g_topk[NROWS * KN];
__device__ int       g_dv[NROWS];
__device__ float     g_invdv[NROWS];

__device__ __forceinline__ uint32_t smem_u32(const void* p) {
    uint32_t a;
    asm("{ .reg .u64 t; cvta.to.shared.u64 t, %1; cvt.u32.u64 %0, t; }" : "=r"(a) : "l"(p));
    return a;
}
// monotone float->uint key (total order incl. negatives)
__device__ __forceinline__ uint32_t fkey(float f) {
    uint32_t u = __float_as_uint(f);
    return (u & 0x80000000u) ? ~u : (u | 0x80000000u);
}
__device__ __forceinline__ float fkeyinv(uint32_t k) {
    return (k & 0x80000000u) ? __uint_as_float(k ^ 0x80000000u) : __uint_as_float(~k);
}

// ---------------- kernel 1: prep — norms, fp16 normalized rows; zero dv ----------------
__global__ __launch_bounds__(256) void k_prep(const float* __restrict__ feats) {
    int warp = (blockIdx.x * blockDim.x + threadIdx.x) >> 5;
    int lane = threadIdx.x & 31;
    if (warp < NROWS) {
        const float* x = feats + (size_t)warp * DDIM;
        float s = 0.f;
        #pragma unroll
        for (int k = lane; k < DDIM; k += 32) { float v = x[k]; s += v * v; }
        #pragma unroll
        for (int off = 16; off; off >>= 1) s += __shfl_xor_sync(0xffffffffu, s, off);
        float inv = 1.0f / sqrtf(s);
        if (lane == 0) g_invn[warp] = inv;
        __half* br = g_Bh + (size_t)warp * DDIM;
        #pragma unroll
        for (int k = lane; k < DDIM; k += 32)
            br[k] = __float2half(x[k] * inv);
    }
    int gt = blockIdx.x * blockDim.x + threadIdx.x;
    if (gt < NROWS) g_dv[gt] = 0;
}

// ---------------- kernel 2: symmetric HMMA GEMM (upper-triangle tiles + mirror),
//                  half store, block-max epilogue, folded output zeroing ----------------
#define BM 128
#define BK 32
#define STAGES 3
#define KITER (DDIM / BK)          // 8
#define SSTRIDE 40
#define STAGE_HALF (BM * SSTRIDE)
#define STAGE_BYTES (2 * STAGE_HALF * 2)
#define GEMM_SMEM (STAGES * STAGE_BYTES)   // 61440
#define NTRI (NTB * (NTB + 1) / 2)         // 2080
// epilogue smem offsets (bytes, within the same dynamic smem)
#define EP_STAGE   0                        // 128 x 136 halves = 34816
#define EP_COLMAX  34816                    // 128 u32 = 512
#define EP_SMAX    35840                    // 256 u32 = 1024

__device__ __forceinline__ void ldsm_x4(uint32_t* r, uint32_t addr) {
    asm volatile("ldmatrix.sync.aligned.m8n8.x4.shared.b16 {%0,%1,%2,%3}, [%4];"
                 : "=r"(r[0]), "=r"(r[1]), "=r"(r[2]), "=r"(r[3]) : "r"(addr));
}
__device__ __forceinline__ void mma16816(float* c, const uint32_t* a, uint32_t b0, uint32_t b1) {
    asm volatile("mma.sync.aligned.m16n8k16.row.col.f32.f16.f16.f32 "
                 "{%0,%1,%2,%3}, {%4,%5,%6,%7}, {%8,%9}, {%0,%1,%2,%3};"
                 : "+f"(c[0]), "+f"(c[1]), "+f"(c[2]), "+f"(c[3])
                 : "r"(a[0]), "r"(a[1]), "r"(a[2]), "r"(a[3]), "r"(b0), "r"(b1));
}

__global__ __launch_bounds__(256, 2) void k_gemm(float4* __restrict__ out4) {
    extern __shared__ __half smem[];
    uint32_t sbase = smem_u32(smem);
    int tid = threadIdx.x, lane = tid & 31, wid = tid >> 5;

    // upper-triangle tile decode
    int t = blockIdx.x, by = 0;
    #pragma unroll 1
    for (int r = 0; r < NTB; r++) { int len = NTB - r; if (t < len) { by = r; break; } t -= len; }
    int bx = by + t;
    int bm = by * BM, bn = bx * BM;
    bool diag = (bx == by);

    // folded output zeroing (grid-stride over 16.7M float4)
    {
        float4 z = make_float4(0.f, 0.f, 0.f, 0.f);
        size_t n4 = (size_t)NROWS * NROWS / 4;
        size_t stride = (size_t)gridDim.x * 256;
        for (size_t i = (size_t)blockIdx.x * 256 + tid; i < n4; i += stride) out4[i] = z;
    }

    int wm0 = (wid >> 1) * 32;
    int wn0 = (wid & 1) * 64;
    int r0 = tid >> 2, s0 = tid & 3;
    int r1 = (tid + 256) >> 2, s1 = (tid + 256) & 3;
    const __half* gA = g_Bh + (size_t)bm * DDIM;
    const __half* gB = g_Bh + (size_t)bn * DDIM;

    float acc[2][8][4];
    #pragma unroll
    for (int mt = 0; mt < 2; mt++)
        #pragma unroll
        for (int nt = 0; nt < 8; nt++)
            #pragma unroll
            for (int i = 0; i < 4; i++) acc[mt][nt][i] = 0.f;

    #pragma unroll
    for (int s = 0; s < STAGES - 1; s++) {
        int k0 = s * BK;
        uint32_t sa = sbase + s * STAGE_BYTES;
        uint32_t sbm = sa + STAGE_HALF * 2;
        asm volatile("cp.async.cg.shared.global [%0], [%1], 16;" ::
                     "r"(sa + (r0 * SSTRIDE + s0 * 8) * 2), "l"(gA + (size_t)r0 * DDIM + k0 + s0 * 8));
        asm volatile("cp.async.cg.shared.global [%0], [%1], 16;" ::
                     "r"(sa + (r1 * SSTRIDE + s1 * 8) * 2), "l"(gA + (size_t)r1 * DDIM + k0 + s1 * 8));
        asm volatile("cp.async.cg.shared.global [%0], [%1], 16;" ::
                     "r"(sbm + (r0 * SSTRIDE + s0 * 8) * 2), "l"(gB + (size_t)r0 * DDIM + k0 + s0 * 8));
        asm volatile("cp.async.cg.shared.global [%0], [%1], 16;" ::
                     "r"(sbm + (r1 * SSTRIDE + s1 * 8) * 2), "l"(gB + (size_t)r1 * DDIM + k0 + s1 * 8));
        asm volatile("cp.async.commit_group;");
    }

    for (int i = 0; i < KITER; i++) {
        asm volatile("cp.async.wait_group %0;" :: "n"(STAGES - 2));
        __syncthreads();
        int st = i % STAGES;
        uint32_t As = sbase + st * STAGE_BYTES;
        uint32_t Bs = As + STAGE_HALF * 2;

        #pragma unroll
        for (int ks = 0; ks < 2; ks++) {
            uint32_t a[2][4];
            #pragma unroll
            for (int mt = 0; mt < 2; mt++)
                ldsm_x4(a[mt], As + ((wm0 + mt * 16 + (lane & 15)) * SSTRIDE + ks * 16 + (lane >> 4) * 8) * 2);
            #pragma unroll
            for (int ng = 0; ng < 4; ng++) {
                uint32_t b[4];
                ldsm_x4(b, Bs + ((wn0 + ng * 16 + (lane & 15)) * SSTRIDE + ks * 16 + (lane >> 4) * 8) * 2);
                #pragma unroll
                for (int mt = 0; mt < 2; mt++) {
                    mma16816(acc[mt][ng * 2 + 0], a[mt], b[0], b[2]);
                    mma16816(acc[mt][ng * 2 + 1], a[mt], b[1], b[3]);
                }
            }
        }

        int pf = i + STAGES - 1;
        if (pf < KITER) {
            int k0 = pf * BK;
            uint32_t sa = sbase + (pf % STAGES) * STAGE_BYTES;
            uint32_t sbm = sa + STAGE_HALF * 2;
            asm volatile("cp.async.cg.shared.global [%0], [%1], 16;" ::
                         "r"(sa + (r0 * SSTRIDE + s0 * 8) * 2), "l"(gA + (size_t)r0 * DDIM + k0 + s0 * 8));
            asm volatile("cp.async.cg.shared.global [%0], [%1], 16;" ::
                         "r"(sa + (r1 * SSTRIDE + s1 * 8) * 2), "l"(gA + (size_t)r1 * DDIM + k0 + s1 * 8));
            asm volatile("cp.async.cg.shared.global [%0], [%1], 16;" ::
                         "r"(sbm + (r0 * SSTRIDE + s0 * 8) * 2), "l"(gB + (size_t)r0 * DDIM + k0 + s0 * 8));
            asm volatile("cp.async.cg.shared.global [%0], [%1], 16;" ::
                         "r"(sbm + (r1 * SSTRIDE + s1 * 8) * 2), "l"(gB + (size_t)r1 * DDIM + k0 + s1 * 8));
        }
        asm volatile("cp.async.commit_group;");
        __syncthreads();
    }

    asm volatile("cp.async.wait_group 0;" ::);
    __syncthreads();

    char* smc = (char*)smem;
    uint32_t* smax = (uint32_t*)(smc + EP_SMAX);      // [128][2]
    if (tid < 256) smax[tid] = 0;
    __syncthreads();

    const float NEG_INF = __int_as_float(0xff800000);
    int gid = lane >> 2, tig = lane & 3;

    // ---- direct store (rows bm.., cols bn..) + row maxima of STORED halves ----
    #pragma unroll
    for (int mt = 0; mt < 2; mt++) {
        int row = bm + wm0 + mt * 16 + gid;
        float mx0 = NEG_INF, mx1 = NEG_INF;
        #pragma unroll
        for (int nt = 0; nt < 8; nt++) {
            int col = bn + wn0 + nt * 8 + 2 * tig;
            __half2 h0 = __floats2half2_rn(acc[mt][nt][0], acc[mt][nt][1]);
            __half2 h1 = __floats2half2_rn(acc[mt][nt][2], acc[mt][nt][3]);
            *(__half2*)(g_simh + (size_t)row * NROWS + col) = h0;
            *(__half2*)(g_simh + (size_t)(row + 8) * NROWS + col) = h1;
            float2 f0 = __half22float2(h0), f1 = __half22float2(h1);
            mx0 = fmaxf(mx0, fmaxf(f0.x, f0.y));
            mx1 = fmaxf(mx1, fmaxf(f1.x, f1.y));
        }
        mx0 = fmaxf(mx0, __shfl_xor_sync(0xffffffffu, mx0, 1));
        mx0 = fmaxf(mx0, __shfl_xor_sync(0xffffffffu, mx0, 2));
        mx1 = fmaxf(mx1, __shfl_xor_sync(0xffffffffu, mx1, 1));
        mx1 = fmaxf(mx1, __shfl_xor_sync(0xffffffffu, mx1, 2));
        if (tig == 0) {
            smax[(wm0 + mt * 16 + gid) * 2 + (wid & 1)] = fkey(mx0);
            smax[(wm0 + mt * 16 + 8 + gid) * 2 + (wid & 1)] = fkey(mx1);
        }
    }
    __syncthreads();
    if (tid < 128) {
        uint32_t k = max(smax[tid * 2], smax[tid * 2 + 1]);
        g_bmax[(size_t)(bm + tid) * NTB + bx] = k;
    }

    // ---- mirror (off-diagonal): transpose via smem, store rows bn.., cols bm.. ----
    if (!diag) {
        __half*   stage  = (__half*)(smc + EP_STAGE);     // [col][row] 128 x 136
        uint32_t* colmax = (uint32_t*)(smc + EP_COLMAX);  // [128]
        if (tid < 128) colmax[tid] = 0;
        __syncthreads();

        #pragma unroll
        for (int nt = 0; nt < 8; nt++) {
            #pragma unroll
            for (int e = 0; e < 2; e++) {
                int col = wn0 + nt * 8 + 2 * tig + e;       // 0..127 (tile col)
                float cm = NEG_INF;
                #pragma unroll
                for (int mt = 0; mt < 2; mt++) {
                    #pragma unroll
                    for (int h = 0; h < 2; h++) {
                        float v = acc[mt][nt][h * 2 + e];
                        __half hv = __float2half_rn(v);
                        int rowi = wm0 + mt * 16 + h * 8 + gid; // 0..127 (tile row)
                        stage[col * 136 + rowi] = hv;
                        cm = fmaxf(cm, __half2float(hv));
                    }
                }
                // reduce col max over gid lanes (stride 4,8,16)
                cm = fmaxf(cm, __shfl_xor_sync(0xffffffffu, cm, 4));
                cm = fmaxf(cm, __shfl_xor_sync(0xffffffffu, cm, 8));
                cm = fmaxf(cm, __shfl_xor_sync(0xffffffffu, cm, 16));
                if (gid == 0) atomicMax(&colmax[col], fkey(cm));
            }
        }
        __syncthreads();

        // write out transposed tile: 2048 uint4 chunks (8 halves each)
        #pragma unroll
        for (int i = 0; i < 8; i++) {
            int c = tid + i * 256;
            int trow = c >> 4, tc = c & 15;
            uint4 v = *(uint4*)(stage + trow * 136 + tc * 8);
            *(uint4*)(g_simh + (size_t)(bn + trow) * NROWS + bm + tc * 8) = v;
        }
        if (tid < 128)
            g_bmax[(size_t)(bn + tid) * NTB + by] = colmax[tid];
    }
}

// ---------------- kernel 3: theta = 20th largest of 64 block maxima + block mask ----------------
__global__ __launch_bounds__(256) void k_theta() {
    int row = blockIdx.x * 8 + (threadIdx.x >> 5);
    int lane = threadIdx.x & 31;
    const uint32_t* bk = g_bmax + (size_t)row * NTB;
    uint32_t v0 = bk[lane], v1 = bk[lane + 32];
    uint32_t v0o = v0, v1o = v1;
    uint32_t M = 0;
    #pragma unroll 1
    for (int r = 0; r < 20; r++) {
        uint32_t lm = max(v0, v1);
        M = lm;
        #pragma unroll
        for (int off = 16; off; off >>= 1) M = max(M, __shfl_xor_sync(0xffffffffu, M, off));
        unsigned b = __ballot_sync(0xffffffffu, lm == M);
        if (lane == __ffs(b) - 1) { if (v0 == M) v0 = 0; else v1 = 0; }
    }
    unsigned m0 = __ballot_sync(0xffffffffu, v0o >= M);
    unsigned m1 = __ballot_sync(0xffffffffu, v1o >= M);
    if (lane == 0) {
        g_theta[row] = fkeyinv(M);
        g_bmask[row] = (unsigned long long)m0 | ((unsigned long long)m1 << 32);
    }
}

// ---------------- kernel 4: masked candidate gather + exact rescore + exact top-10 ----------------
#define TCAP 512
__device__ __forceinline__ void topk_ins(float v, int j, float* bv, int* bi) {
    if (v > bv[KN - 1] || (v == bv[KN - 1] && j < bi[KN - 1])) {
        float cv = v; int ci = j;
        #pragma unroll
        for (int t = 0; t < KN; t++) {
            bool better = (cv > bv[t]) || (cv == bv[t] && ci < bi[t]);
            if (better) {
                float tv = bv[t]; int ti = bi[t];
                bv[t] = cv; bi[t] = ci;
                cv = tv; ci = ti;
            }
        }
    }
}
__device__ __forceinline__ void scan_block(int row, int b, int lane, float theta,
                                           int w, int* sli, int* scnt) {
    uint2 q = *(const uint2*)(g_simh + (size_t)row * NROWS + b * 128 + lane * 4);
    __half2 p0 = *(__half2*)&q.x, p1 = *(__half2*)&q.y;
    float2 f0 = __half22float2(p0), f1 = __half22float2(p1);
    float m = fmaxf(fmaxf(f0.x, f0.y), fmaxf(f1.x, f1.y));
    if (m >= theta) {
        int jb = b * 128 + lane * 4;
        if (f0.x >= theta) { int p = atomicAdd(&scnt[w], 1); if (p < TCAP) sli[p] = jb + 0; }
        if (f0.y >= theta) { int p = atomicAdd(&scnt[w], 1); if (p < TCAP) sli[p] = jb + 1; }
        if (f1.x >= theta) { int p = atomicAdd(&scnt[w], 1); if (p < TCAP) sli[p] = jb + 2; }
        if (f1.y >= theta) { int p = atomicAdd(&scnt[w], 1); if (p < TCAP) sli[p] = jb + 3; }
    }
}

__global__ __launch_bounds__(256) void k_topk(const float* __restrict__ feats) {
    __shared__ float slv[8][TCAP];
    __shared__ int   sli[8][TCAP];
    __shared__ int   scnt[8];
    int w = threadIdx.x >> 5, lane = threadIdx.x & 31;
    int row = blockIdx.x * 8 + w;
    const float NEG_INF = __int_as_float(0xff800000);
    float theta = g_theta[row];
    unsigned long long mask = g_bmask[row];
    if (lane == 0) scnt[w] = 0;
    __syncwarp();

    // scan only flagged blocks (>= theta can only occur where bmax >= theta)
    while (mask) {
        int b0 = __ffsll(mask) - 1; mask &= mask - 1;
        int b1 = -1;
        if (mask) { b1 = __ffsll(mask) - 1; mask &= mask - 1; }
        scan_block(row, b0, lane, theta, w, sli[w], scnt);
        if (b1 >= 0) scan_block(row, b1, lane, theta, w, sli[w], scnt);
    }
    __syncwarp();
    int cnt = scnt[w];

    float bv[KN]; int bi[KN];
    #pragma unroll
    for (int t = 0; t < KN; t++) { bv[t] = NEG_INF; bi[t] = 0x7fffffff; }

    const float4* fr = (const float4*)(feats + (size_t)row * DDIM);
    if (cnt <= TCAP) {
        // exact fp32 rescore: sim = dot(feats_row, feats_j) * invn_j
        for (int i = lane; i < cnt; i += 32) {
            int j = sli[w][i];
            const float4* fj = (const float4*)(feats + (size_t)j * DDIM);
            float s = 0.f;
            #pragma unroll 8
            for (int k = 0; k < DDIM / 4; k++) {
                float4 a = fr[k], b = fj[k];
                s += a.x * b.x + a.y * b.y + a.z * b.z + a.w * b.w;
            }
            slv[w][i] = s * g_invn[j];
        }
        __syncwarp();
        for (int i = lane; i < cnt; i += 32) topk_ins(slv[w][i], sli[w][i], bv, bi);
    } else {
        // exact fallback (never expected): full exact rescore of the row
        for (int j = lane; j < NROWS; j += 32) {
            const float4* fj = (const float4*)(feats + (size_t)j * DDIM);
            float s = 0.f;
            #pragma unroll 8
            for (int k = 0; k < DDIM / 4; k++) {
                float4 a = fr[k], b = fj[k];
                s += a.x * b.x + a.y * b.y + a.z * b.z + a.w * b.w;
            }
            topk_ins(s * g_invn[j], j, bv, bi);
        }
    }

    // 10 rounds of warp argmax ((v desc, idx asc) comparator) with pop
    #pragma unroll 1
    for (int r = 0; r < KN; r++) {
        float mv = bv[0]; int mi = bi[0];
        #pragma unroll
        for (int off = 16; off; off >>= 1) {
            float ov = __shfl_xor_sync(0xffffffffu, mv, off);
            int   oi = __shfl_xor_sync(0xffffffffu, mi, off);
            if (ov > mv || (ov == mv && oi < mi)) { mv = ov; mi = oi; }
        }
        if (mi == bi[0]) {
            #pragma unroll
            for (int t = 0; t < KN - 1; t++) { bv[t] = bv[t + 1]; bi[t] = bi[t + 1]; }
            bv[KN - 1] = NEG_INF; bi[KN - 1] = 0x7fffffff;
        }
        if (lane == 0) {
            g_topk[row * KN + r] = mi;
            atomicAdd(&g_dv[mi], 1);
        }
    }
}

// ---------------- kernel 5: inv_dv ----------------
__global__ void k_invdv() {
    int i = blockIdx.x * blockDim.x + threadIdx.x;
    if (i < NROWS) {
        int d = g_dv[i];
        g_invdv[i] = d > 0 ? 1.0f / sqrtf((float)d) : 0.0f;
    }
}

// ---------------- kernel 6: scatter 10x10 outer products per hyperedge ----------------
__global__ __launch_bounds__(128) void k_scatter(float* __restrict__ out) {
    __shared__ int   sidx[KN];
    __shared__ float sw[KN];
    int e = blockIdx.x;
    int t = threadIdx.x;
    if (t < KN) {
        int a = g_topk[e * KN + t];
        sidx[t] = a;
        sw[t] = g_invdv[a];
    }
    __syncthreads();
    if (t < KN * KN) {
        int a = sidx[t / KN];
        int b = sidx[t % KN];
        float val = (0.1f * sw[t / KN]) * sw[t % KN];
        atomicAdd(&out[(size_t)a * NROWS + b], val);
    }
}

// ---------------- launch ----------------
extern "C" void kernel_launch(void* const* d_in, const int* in_sizes, int n_in,
                              void* d_out, int out_size) {
    const float* feats = (const float*)d_in[0];
    float* out = (float*)d_out;

    k_prep<<<(NROWS * 32) / 256, 256>>>(feats);

    cudaFuncSetAttribute(k_gemm, cudaFuncAttributeMaxDynamicSharedMemorySize, GEMM_SMEM);
    k_gemm<<<NTRI, 256, GEMM_SMEM>>>((float4*)out);

    k_theta<<<NROWS / 8, 256>>>();
    k_topk<<<NROWS / 8, 256>>>(feats);
    k_invdv<<<NROWS / 256, 256>>>();
    k_scatter<<<NROWS, 128>>>(out);
}